// round 4
// baseline (speedup 1.0000x reference)
#include <cuda_runtime.h>
#include <cstdint>

// Problem constants
#define B 4
#define H 128
#define W 128
#define BINS 64
#define CBINS 32         // bins handled per CTA (bin-split 2)
#define KK 26            // 25 neighbors + current
#define KS 5

// Tiling: 4 x 32 output pixels per CTA, halo 2 -> 8 x 36 staged pixels
#define TH 4
#define TW 32
#define PH (TH + 4)      // 8
#define PW (TW + 4)      // 36
#define NPIX (PH * PW)   // 288 staged pixels
#define AS 132           // attn k-stride in floats (16B aligned for float4 reads)
#define THREADS 256

#define SREF_FLOATS (NPIX * CBINS)     // 9216  (36.9 KB, [pix][bin32])
#define SATTN_FLOATS (KK * AS)         // 3432  (13.7 KB)
#define SMEM_BYTES ((SREF_FLOATS + SATTN_FLOATS) * 4)   // 50592 B -> 4 CTAs/SM

typedef unsigned long long ull;

__device__ __forceinline__ void cp_async16(uint32_t dst, const void* src, int src_bytes) {
    asm volatile("cp.async.cg.shared.global [%0], [%1], 16, %2;\n"
                 :: "r"(dst), "l"(src), "r"(src_bytes) : "memory");
}

// LDS.128 -> two packed f32x2 operands
__device__ __forceinline__ void lds_v2u64(ull& a, ull& b, uint32_t addr) {
    asm volatile("ld.shared.v2.u64 {%0, %1}, [%2];"
                 : "=l"(a), "=l"(b) : "r"(addr));
}

// packed fp32x2 FMA: d = a*b + d (elementwise on two f32 lanes)
__device__ __forceinline__ void fma2(ull& d, ull a, ull b) {
    asm volatile("fma.rn.f32x2 %0, %1, %2, %0;" : "+l"(d) : "l"(a), "l"(b));
}

__device__ __forceinline__ ull pack2(float a) {
    ull r;
    asm("mov.b64 %0, {%1, %1};" : "=l"(r) : "f"(a));
    return r;
}

__device__ __forceinline__ void unpack2(float& lo, float& hi, ull v) {
    asm("mov.b64 {%0, %1}, %2;" : "=f"(lo), "=f"(hi) : "l"(v));
}

__global__ __launch_bounds__(THREADS, 4)
void agg_kernel(const float* __restrict__ attn,
                const float* __restrict__ refv,
                const float* __restrict__ curv,
                float* __restrict__ out) {
    extern __shared__ float smem[];
    float* s_ref  = smem;                 // [pix][32 bins], pix = lr*PW + lc
    float* s_attn = smem + SREF_FLOATS;   // [k][pix], pix = r*TW + c, stride AS

    const int tid  = threadIdx.x;
    const int bidx = blockIdx.x;          // 1024 blocks: 2 bs x 4 tw x 32 th x 4 b
    const int bs = bidx & 1;
    const int tw = (bidx >> 1) & 3;
    const int th = (bidx >> 3) & 31;
    const int b  = bidx >> 8;
    const int h0 = th * TH;
    const int w0 = tw * TW;
    const int bo = bs * CBINS;            // bin offset of this CTA

    const float* refb = refv + (size_t)b * H * W * BINS + bo;

    // ---------- Stage ref tile+halo (this CTA's 32 bins) via cp.async ----------
    // 288 pixels * 8 float4-chunks = 2304 chunks = 9 per thread.
    const uint32_t s_ref_b = (uint32_t)__cvta_generic_to_shared(s_ref);
    #pragma unroll
    for (int i = 0; i < (NPIX * 8) / THREADS; ++i) {
        int idx = tid + i * THREADS;
        int g   = idx & 7;               // float4 chunk within the 32-bin record
        int pix = idx >> 3;
        int lr  = pix / PW;
        int lc  = pix - lr * PW;
        int gh  = h0 + lr - 2;
        int gw  = w0 + lc - 2;
        bool ok = ((unsigned)gh < (unsigned)H) && ((unsigned)gw < (unsigned)W);
        const float* src = refb + (((ok ? gh : 0) * W + (ok ? gw : 0)) * BINS + g * 4);
        uint32_t dst = s_ref_b + (uint32_t)((pix * CBINS + g * 4) * 4);
        cp_async16(dst, src, ok ? 16 : 0);   // zero-fill halo
    }
    asm volatile("cp.async.commit_group;\n" ::: "memory");

    // ---------- Stage attn tile, transposed [k][pix] (coalesced reads) ----------
    #pragma unroll 1
    for (int idx = tid; idx < TH * TW * KK; idx += THREADS) {
        int pix = idx / KK;
        int k   = idx - pix * KK;
        int r   = pix >> 5;
        int c   = pix & 31;
        float a = attn[(((b * H + h0 + r) * W) + (w0 + c)) * KK + k];
        s_attn[k * AS + pix] = a;
    }

    asm volatile("cp.async.wait_group 0;\n" ::: "memory");
    __syncthreads();

    // ---------- Compute: thread = 4 adjacent px (one row) x 4 bins (2 f32x2) ----------
    const int bg = tid & 7;              // 4-bin group within CTA's 32 bins
    const int pg = tid >> 3;             // 0..31
    const int r  = pg >> 3;              // output row 0..3
    const int c0 = (pg & 7) * 4;         // first output col 0,4,...,28

    ull acc[4][2];
    #pragma unroll
    for (int p = 0; p < 4; ++p) { acc[p][0] = 0ull; acc[p][1] = 0ull; }

    const float* arow_base = s_attn + r * TW + c0;

    #pragma unroll
    for (int di = 0; di < 5; ++di) {
        // staged row (r+di), cols c0 .. c0+7 needed across dj
        const uint32_t vb = s_ref_b +
            (uint32_t)((((r + di) * PW + c0) * CBINS + bg * 4) * 4);
        ull v[8][2];
        #pragma unroll
        for (int j = 0; j < 4; ++j)
            lds_v2u64(v[j][0], v[j][1], vb + j * (CBINS * 4));

        #pragma unroll
        for (int dj = 0; dj < 5; ++dj) {
            if (dj < 4)   // rolling window: prefetch next column during FMAs
                lds_v2u64(v[dj + 4][0], v[dj + 4][1], vb + (dj + 4) * (CBINS * 4));
            // attn for 4 px at this tap: one broadcast LDS.128
            float4 a4 = *reinterpret_cast<const float4*>(arow_base + (di * KS + dj) * AS);
            ull ap0 = pack2(a4.x), ap1 = pack2(a4.y), ap2 = pack2(a4.z), ap3 = pack2(a4.w);
            fma2(acc[0][0], v[0 + dj][0], ap0);
            fma2(acc[0][1], v[0 + dj][1], ap0);
            fma2(acc[1][0], v[1 + dj][0], ap1);
            fma2(acc[1][1], v[1 + dj][1], ap1);
            fma2(acc[2][0], v[2 + dj][0], ap2);
            fma2(acc[2][1], v[2 + dj][1], ap2);
            fma2(acc[3][0], v[3 + dj][0], ap3);
            fma2(acc[3][1], v[3 + dj][1], ap3);
        }
    }

    // ---------- Epilogue: += attn[25]*current, direct coalesced float4 ----------
    const float* curb = curv + (size_t)b * H * W * BINS + bo;
    float*       outb = out  + (size_t)b * H * W * BINS + bo;
    const float* a25  = s_attn + 25 * AS + r * TW + c0;
    #pragma unroll
    for (int p = 0; p < 4; ++p) {
        int gaddr = ((h0 + r) * W + (w0 + c0 + p)) * BINS + bg * 4;
        float4 cv = *reinterpret_cast<const float4*>(curb + gaddr);
        float a = a25[p];
        float ax, ay, az, aw;
        unpack2(ax, ay, acc[p][0]);
        unpack2(az, aw, acc[p][1]);
        float4 o;
        o.x = fmaf(a, cv.x, ax);
        o.y = fmaf(a, cv.y, ay);
        o.z = fmaf(a, cv.z, az);
        o.w = fmaf(a, cv.w, aw);
        *reinterpret_cast<float4*>(outb + gaddr) = o;
    }
}

extern "C" void kernel_launch(void* const* d_in, const int* in_sizes, int n_in,
                              void* d_out, int out_size) {
    const float* attn = (const float*)d_in[0];   // [4,128,128,26]
    const float* refv = (const float*)d_in[1];   // [4,128,128,64]
    const float* curv = (const float*)d_in[2];   // [4,128,128,64]
    float* out = (float*)d_out;                  // [4,128,128,64]

    cudaFuncSetAttribute(agg_kernel, cudaFuncAttributeMaxDynamicSharedMemorySize,
                         SMEM_BYTES);

    const int nblocks = 2 * B * (H / TH) * (W / TW);   // 2*4*32*4 = 1024
    agg_kernel<<<nblocks, THREADS, SMEM_BYTES>>>(attn, refv, curv, out);
}

// round 5
// speedup vs baseline: 1.2462x; 1.2462x over previous
#include <cuda_runtime.h>
#include <cstdint>

// Problem constants
#define B 4
#define H 128
#define W 128
#define BINS 64
#define KK 26            // 25 neighbors + current
#define KS 5

// Tiling: 4 x 32 output pixels per CTA, halo 2 -> 8 x 36 staged pixels
#define TH 4
#define TW 32
#define PH (TH + 4)      // 8
#define PW (TW + 4)      // 36
#define NPIX (PH * PW)   // 288 staged pixels
#define AS2 132          // attn k-stride in u64 units (row start 16B-aligned)
#define THREADS 256

#define SREF_FLOATS (NPIX * BINS)              // 18432 -> 73728 B
#define SATTN_U64   (KK * AS2)                 // 3432  -> 27456 B
#define SMEM_BYTES  (SREF_FLOATS * 4 + SATTN_U64 * 8)   // 101184 B -> 2 CTAs/SM

typedef unsigned long long ull;

__device__ __forceinline__ void cp_async16(uint32_t dst, const void* src, int src_bytes) {
    asm volatile("cp.async.cg.shared.global [%0], [%1], 16, %2;\n"
                 :: "r"(dst), "l"(src), "r"(src_bytes) : "memory");
}

// LDS.128 -> two packed u64 (each holding 2 fp32 lanes)
__device__ __forceinline__ void lds_v2u64(ull& a, ull& b, uint32_t addr) {
    asm volatile("ld.shared.v2.u64 {%0, %1}, [%2];"
                 : "=l"(a), "=l"(b) : "r"(addr));
}

__device__ __forceinline__ ull lds_u64(uint32_t addr) {
    ull r;
    asm volatile("ld.shared.u64 %0, [%1];" : "=l"(r) : "r"(addr));
    return r;
}

// packed fp32x2 FMA: d = a*b + d
__device__ __forceinline__ void fma2(ull& d, ull a, ull b) {
    asm volatile("fma.rn.f32x2 %0, %1, %2, %0;" : "+l"(d) : "l"(a), "l"(b));
}

__device__ __forceinline__ ull pack2(float a) {
    ull r;
    asm("mov.b64 %0, {%1, %1};" : "=l"(r) : "f"(a));
    return r;
}

__global__ __launch_bounds__(THREADS, 2)
void agg_kernel(const float* __restrict__ attn,
                const float* __restrict__ refv,
                const float* __restrict__ curv,
                float* __restrict__ out) {
    extern __shared__ float smem[];
    float* s_ref   = smem;                                   // [pix][64], pix = lr*PW+lc
    ull*   s_attn2 = (ull*)(smem + SREF_FLOATS);             // [k][pix] packed {a,a}

    const int tid  = threadIdx.x;
    const int bidx = blockIdx.x;          // 512 blocks: 4 tw x 32 th x 4 batch
    const int tw = bidx & 3;
    const int th = (bidx >> 2) & 31;
    const int b  = bidx >> 7;
    const int h0 = th * TH;
    const int w0 = tw * TW;

    const float* refb = refv + (size_t)b * H * W * BINS;

    // ---------- Stage ref tile+halo via cp.async (natural [pix][bin]) ----------
    const uint32_t s_ref_b = (uint32_t)__cvta_generic_to_shared(s_ref);
    #pragma unroll
    for (int i = 0; i < (NPIX * 16) / THREADS; ++i) {
        int idx = tid + i * THREADS;
        int g   = idx & 15;
        int pix = idx >> 4;
        int lr  = pix / PW;
        int lc  = pix - lr * PW;
        int gh  = h0 + lr - 2;
        int gw  = w0 + lc - 2;
        bool ok = ((unsigned)gh < (unsigned)H) && ((unsigned)gw < (unsigned)W);
        const float* src = refb + (((ok ? gh : 0) * W + (ok ? gw : 0)) * BINS + g * 4);
        uint32_t dst = s_ref_b + (uint32_t)((pix * BINS + g * 4) * 4);
        cp_async16(dst, src, ok ? 16 : 0);   // zero-fill halo
    }
    asm volatile("cp.async.commit_group;\n" ::: "memory");

    // ---------- Stage attn, transposed [k][pix], DUPLICATED as {a,a} u64 ----------
    #pragma unroll 1
    for (int idx = tid; idx < TH * TW * KK; idx += THREADS) {
        int pix = idx / KK;
        int k   = idx - pix * KK;
        int r   = pix >> 5;
        int c   = pix & 31;
        float a = attn[(((b * H + h0 + r) * W) + (w0 + c)) * KK + k];
        s_attn2[k * AS2 + pix] = pack2(a);
    }

    asm volatile("cp.async.wait_group 0;\n" ::: "memory");
    __syncthreads();

    // ---------- Compute: thread = 8 adjacent px (one row) x 4 bins ----------
    const int bg = tid & 15;             // float4 bin group 0..15
    const int pg = tid >> 4;             // 0..15
    const int r  = pg >> 2;              // output row 0..3
    const int c0 = (pg & 3) * 8;         // first output col (even -> 16B attn align)

    ull acc[8][2];
    #pragma unroll
    for (int p = 0; p < 8; ++p) { acc[p][0] = 0ull; acc[p][1] = 0ull; }

    const uint32_t s_attn_b = (uint32_t)__cvta_generic_to_shared(s_attn2)
                            + (uint32_t)((r * TW + c0) * 8);

    #pragma unroll
    for (int di = 0; di < 5; ++di) {
        // 12-wide sliding window of ref vectors (8 outputs + 4 halo)
        const uint32_t vb = s_ref_b +
            (uint32_t)((((r + di) * PW + c0) * BINS + bg * 4) * 4);
        ull v[12][2];
        #pragma unroll
        for (int j = 0; j < 12; ++j)
            lds_v2u64(v[j][0], v[j][1], vb + j * (BINS * 4));

        #pragma unroll
        for (int dj = 0; dj < 5; ++dj) {
            const uint32_t ab = s_attn_b + (uint32_t)((di * KS + dj) * AS2 * 8);
            // 8 packed attn pairs via 4 LDS.128 (2 px per load, broadcast)
            ull ap[8];
            #pragma unroll
            for (int q = 0; q < 4; ++q)
                lds_v2u64(ap[2 * q], ap[2 * q + 1], ab + q * 16);
            #pragma unroll
            for (int p = 0; p < 8; ++p) {
                fma2(acc[p][0], v[p + dj][0], ap[p]);
                fma2(acc[p][1], v[p + dj][1], ap[p]);
            }
        }
    }

    // ---------- Epilogue: += attn[25]*current, direct 128-bit stores ----------
    const float* curb = curv + (size_t)b * H * W * BINS;
    float*       outb = out  + (size_t)b * H * W * BINS;
    const uint32_t a25b = (uint32_t)__cvta_generic_to_shared(s_attn2)
                        + (uint32_t)((25 * AS2 + r * TW + c0) * 8);
    #pragma unroll
    for (int p = 0; p < 8; ++p) {
        int gaddr = ((h0 + r) * W + (w0 + c0 + p)) * BINS + bg * 4;
        ulonglong2 cv = *reinterpret_cast<const ulonglong2*>(curb + gaddr);
        ull a = lds_u64(a25b + p * 8);
        fma2(acc[p][0], cv.x, a);
        fma2(acc[p][1], cv.y, a);
        ulonglong2 o;
        o.x = acc[p][0];
        o.y = acc[p][1];
        *reinterpret_cast<ulonglong2*>(outb + gaddr) = o;
    }
}

extern "C" void kernel_launch(void* const* d_in, const int* in_sizes, int n_in,
                              void* d_out, int out_size) {
    const float* attn = (const float*)d_in[0];   // [4,128,128,26]
    const float* refv = (const float*)d_in[1];   // [4,128,128,64]
    const float* curv = (const float*)d_in[2];   // [4,128,128,64]
    float* out = (float*)d_out;                  // [4,128,128,64]

    cudaFuncSetAttribute(agg_kernel, cudaFuncAttributeMaxDynamicSharedMemorySize,
                         SMEM_BYTES);

    const int nblocks = B * (H / TH) * (W / TW);   // 4*32*4 = 512
    agg_kernel<<<nblocks, THREADS, SMEM_BYTES>>>(attn, refv, curv, out);
}

// round 6
// speedup vs baseline: 1.3116x; 1.0525x over previous
#include <cuda_runtime.h>
#include <cstdint>

// Problem constants
#define B 4
#define H 128
#define W 128
#define BINS 64
#define KK 26            // 25 neighbors + current
#define KS 5

// Tiling: 4 x 32 output pixels per CTA, halo 2 -> 8 x 36 staged pixels
#define TH 4
#define TW 32
#define PH (TH + 4)      // 8
#define PW (TW + 4)      // 36
#define NPIX (PH * PW)   // 288 staged pixels
#define AS 132           // attn k-stride in floats (k*AS is 16B-aligned)
#define THREADS 512

#define SREF_FLOATS (NPIX * BINS)      // 18432 -> 73728 B (natural [pix][bin])
#define SATTN_FLOATS (KK * AS)         // 3432  -> 13728 B
#define SMEM_BYTES ((SREF_FLOATS + SATTN_FLOATS) * 4)   // 87456 B -> 2 CTAs/SM

__device__ __forceinline__ void cp_async16(uint32_t dst, const void* src, int src_bytes) {
    asm volatile("cp.async.cg.shared.global [%0], [%1], 16, %2;\n"
                 :: "r"(dst), "l"(src), "r"(src_bytes) : "memory");
}

__global__ __launch_bounds__(THREADS, 2)
void agg_kernel(const float* __restrict__ attn,
                const float* __restrict__ refv,
                const float* __restrict__ curv,
                float* __restrict__ out) {
    extern __shared__ float smem[];
    float* s_ref  = smem;                 // [pix][64 bins], pix = lr*PW + lc
    float* s_attn = smem + SREF_FLOATS;   // [k][pix], pix = r*TW + c

    const int tid  = threadIdx.x;
    const int bidx = blockIdx.x;          // 512 blocks: 4 tw x 32 th x 4 batch
    const int tw = bidx & 3;
    const int th = (bidx >> 2) & 31;
    const int b  = bidx >> 7;
    const int h0 = th * TH;
    const int w0 = tw * TW;

    const float* refb = refv + (size_t)b * H * W * BINS;

    // ---------- Stage ref tile+halo via cp.async (natural layout) ----------
    // 288 pixels * 16 float4 = 4608 chunks = 9 per thread, fully coalesced.
    const uint32_t s_ref_b = (uint32_t)__cvta_generic_to_shared(s_ref);
    #pragma unroll
    for (int i = 0; i < (NPIX * 16) / THREADS; ++i) {
        int idx = tid + i * THREADS;
        int g   = idx & 15;
        int pix = idx >> 4;
        int lr  = pix / PW;
        int lc  = pix - lr * PW;
        int gh  = h0 + lr - 2;
        int gw  = w0 + lc - 2;
        bool ok = ((unsigned)gh < (unsigned)H) && ((unsigned)gw < (unsigned)W);
        const float* src = refb + (((ok ? gh : 0) * W + (ok ? gw : 0)) * BINS + g * 4);
        uint32_t dst = s_ref_b + (uint32_t)((pix * BINS + g * 4) * 4);
        cp_async16(dst, src, ok ? 16 : 0);   // zero-fill halo
    }
    asm volatile("cp.async.commit_group;\n" ::: "memory");

    // ---------- Stage attn tile, transposed [k][pix] (coalesced reads) ----------
    #pragma unroll 1
    for (int idx = tid; idx < TH * TW * KK; idx += THREADS) {
        int pix = idx / KK;
        int k   = idx - pix * KK;
        int r   = pix >> 5;
        int c   = pix & 31;
        float a = attn[(((b * H + h0 + r) * W) + (w0 + c)) * KK + k];
        s_attn[k * AS + r * TW + c] = a;
    }

    asm volatile("cp.async.wait_group 0;\n" ::: "memory");
    __syncthreads();

    // ---------- Compute: thread = 4 adjacent px (one row) x 4 bins ----------
    const int bg = tid & 15;             // float4 bin group 0..15
    const int pg = tid >> 4;             // 0..31
    const int r  = pg >> 3;              // output row 0..3
    const int c0 = (pg & 7) * 4;         // first output col 0,4,...,28 (16B align)

    float4 acc[4];
    #pragma unroll
    for (int p = 0; p < 4; ++p) acc[p] = make_float4(0.f, 0.f, 0.f, 0.f);

    const float* arow_base = s_attn + r * TW + c0;

    #pragma unroll
    for (int di = 0; di < 5; ++di) {
        // 8-wide sliding window (4 outputs + 4 halo) for staged row (r+di)
        const float* vrow = s_ref + ((r + di) * PW + c0) * BINS + bg * 4;
        float4 v[8];
        #pragma unroll
        for (int j = 0; j < 8; ++j)
            v[j] = *reinterpret_cast<const float4*>(vrow + j * BINS);

        #pragma unroll
        for (int dj = 0; dj < 5; ++dj) {
            // one broadcast LDS.128: attn for this tap, 4 adjacent pixels
            float4 a4 = *reinterpret_cast<const float4*>(arow_base + (di * KS + dj) * AS);
            acc[0].x = fmaf(a4.x, v[0 + dj].x, acc[0].x);
            acc[0].y = fmaf(a4.x, v[0 + dj].y, acc[0].y);
            acc[0].z = fmaf(a4.x, v[0 + dj].z, acc[0].z);
            acc[0].w = fmaf(a4.x, v[0 + dj].w, acc[0].w);
            acc[1].x = fmaf(a4.y, v[1 + dj].x, acc[1].x);
            acc[1].y = fmaf(a4.y, v[1 + dj].y, acc[1].y);
            acc[1].z = fmaf(a4.y, v[1 + dj].z, acc[1].z);
            acc[1].w = fmaf(a4.y, v[1 + dj].w, acc[1].w);
            acc[2].x = fmaf(a4.z, v[2 + dj].x, acc[2].x);
            acc[2].y = fmaf(a4.z, v[2 + dj].y, acc[2].y);
            acc[2].z = fmaf(a4.z, v[2 + dj].z, acc[2].z);
            acc[2].w = fmaf(a4.z, v[2 + dj].w, acc[2].w);
            acc[3].x = fmaf(a4.w, v[3 + dj].x, acc[3].x);
            acc[3].y = fmaf(a4.w, v[3 + dj].y, acc[3].y);
            acc[3].z = fmaf(a4.w, v[3 + dj].z, acc[3].z);
            acc[3].w = fmaf(a4.w, v[3 + dj].w, acc[3].w);
        }
    }

    // ---------- Epilogue: += attn[25]*current, direct coalesced float4 ----------
    const float* curb = curv + (size_t)b * H * W * BINS;
    float*       outb = out  + (size_t)b * H * W * BINS;
    float4 a25 = *reinterpret_cast<const float4*>(arow_base + 25 * AS);
    const float* a25p = &a25.x;
    #pragma unroll
    for (int p = 0; p < 4; ++p) {
        int gaddr = ((h0 + r) * W + (w0 + c0 + p)) * BINS + bg * 4;
        float4 cv = *reinterpret_cast<const float4*>(curb + gaddr);
        float a = a25p[p];
        float4 o;
        o.x = fmaf(a, cv.x, acc[p].x);
        o.y = fmaf(a, cv.y, acc[p].y);
        o.z = fmaf(a, cv.z, acc[p].z);
        o.w = fmaf(a, cv.w, acc[p].w);
        *reinterpret_cast<float4*>(outb + gaddr) = o;
    }
}

extern "C" void kernel_launch(void* const* d_in, const int* in_sizes, int n_in,
                              void* d_out, int out_size) {
    const float* attn = (const float*)d_in[0];   // [4,128,128,26]
    const float* refv = (const float*)d_in[1];   // [4,128,128,64]
    const float* curv = (const float*)d_in[2];   // [4,128,128,64]
    float* out = (float*)d_out;                  // [4,128,128,64]

    cudaFuncSetAttribute(agg_kernel, cudaFuncAttributeMaxDynamicSharedMemorySize,
                         SMEM_BYTES);

    const int nblocks = B * (H / TH) * (W / TW);   // 4*32*4 = 512
    agg_kernel<<<nblocks, THREADS, SMEM_BYTES>>>(attn, refv, curv, out);
}

// round 7
// speedup vs baseline: 1.7780x; 1.3556x over previous
#include <cuda_runtime.h>
#include <cstdint>

// Problem constants
#define B 4
#define H 128
#define W 128
#define BINS 64
#define KK 26            // 25 neighbors + current
#define KS 5

// Tiling: 8 x 16 output pixels per CTA, halo 2 -> 12 x 20 staged pixels
#define TH 8
#define TW 16
#define PH (TH + 4)      // 12
#define PW (TW + 4)      // 20
#define NPIX (PH * PW)   // 240 staged pixels
#define AS 132           // attn k-stride in floats (k*AS 16B-aligned: 132*4=528)
#define THREADS 256

#define SREF_FLOATS (NPIX * BINS)      // 15360 -> 61440 B (natural [pix][bin])
#define SATTN_FLOATS (KK * AS)         // 3432  -> 13728 B
#define SMEM_BYTES ((SREF_FLOATS + SATTN_FLOATS) * 4)   // 75168 B -> 3 CTAs/SM

__device__ __forceinline__ void cp_async16(uint32_t dst, const void* src, int src_bytes) {
    asm volatile("cp.async.cg.shared.global [%0], [%1], 16, %2;\n"
                 :: "r"(dst), "l"(src), "r"(src_bytes) : "memory");
}

__global__ __launch_bounds__(THREADS, 3)
void agg_kernel(const float* __restrict__ attn,
                const float* __restrict__ refv,
                const float* __restrict__ curv,
                float* __restrict__ out) {
    extern __shared__ float smem[];
    float* s_ref  = smem;                 // [pix][64 bins], pix = lr*PW + lc
    float* s_attn = smem + SREF_FLOATS;   // [k][pix], pix = r*TW + c

    const int tid  = threadIdx.x;
    const int bidx = blockIdx.x;          // 512 blocks: 8 tw x 16 th x 4 batch
    const int tw = bidx & 7;
    const int th = (bidx >> 3) & 15;
    const int b  = bidx >> 7;
    const int h0 = th * TH;
    const int w0 = tw * TW;

    const float* refb = refv + (size_t)b * H * W * BINS;

    // ---------- Stage ref tile+halo via cp.async (natural layout) ----------
    // 240 pixels * 16 float4 = 3840 chunks = 15 per thread.
    const uint32_t s_ref_b = (uint32_t)__cvta_generic_to_shared(s_ref);
    #pragma unroll
    for (int i = 0; i < (NPIX * 16) / THREADS; ++i) {
        int idx = tid + i * THREADS;
        int g   = idx & 15;
        int pix = idx >> 4;
        int lr  = pix / PW;
        int lc  = pix - lr * PW;
        int gh  = h0 + lr - 2;
        int gw  = w0 + lc - 2;
        bool ok = ((unsigned)gh < (unsigned)H) && ((unsigned)gw < (unsigned)W);
        const float* src = refb + (((ok ? gh : 0) * W + (ok ? gw : 0)) * BINS + g * 4);
        uint32_t dst = s_ref_b + (uint32_t)((pix * BINS + g * 4) * 4);
        cp_async16(dst, src, ok ? 16 : 0);   // zero-fill halo
    }
    asm volatile("cp.async.commit_group;\n" ::: "memory");

    // ---------- Stage attn tile, transposed [k][pix] (coalesced reads) ----------
    // 8*16*26 = 3328 elements = 13 per thread.
    #pragma unroll
    for (int i = 0; i < (TH * TW * KK) / THREADS; ++i) {
        int idx = tid + i * THREADS;
        int pix = idx / KK;
        int k   = idx - pix * KK;
        float a = attn[((b * H + h0) * W + w0 + ((pix >> 4) * W) + (pix & 15)) * KK + k];
        s_attn[k * AS + pix] = a;
    }

    asm volatile("cp.async.wait_group 0;\n" ::: "memory");
    __syncthreads();

    // ---------- Compute: thread = 2 rows x 4 px x 4 bins (32 outputs) ----------
    const int bg = tid & 15;             // float4 bin group 0..15
    const int pg = tid >> 4;             // 0..15
    const int r0 = (pg >> 2) * 2;        // first output row: 0,2,4,6
    const int c0 = (pg & 3) * 4;         // first output col: 0,4,8,12

    float4 acc0[4], acc1[4];
    #pragma unroll
    for (int p = 0; p < 4; ++p) {
        acc0[p] = make_float4(0.f, 0.f, 0.f, 0.f);
        acc1[p] = make_float4(0.f, 0.f, 0.f, 0.f);
    }

    const float* arow0 = s_attn + r0 * TW + c0;   // attn base, output row r0
    const float* arow1 = arow0 + TW;              // output row r0+1

    // Staged rows r0 .. r0+5: row (r0+arl) serves out-row r0 (di=arl, arl<=4)
    // and out-row r0+1 (di=arl-1, arl>=1) -> 2x vertical reuse of v window.
    #pragma unroll
    for (int arl = 0; arl < 6; ++arl) {
        const float* vrow = s_ref + ((r0 + arl) * PW + c0) * BINS + bg * 4;
        float4 v[8];
        #pragma unroll
        for (int j = 0; j < 8; ++j)
            v[j] = *reinterpret_cast<const float4*>(vrow + j * BINS);

        #pragma unroll
        for (int dj = 0; dj < 5; ++dj) {
            if (arl <= 4) {   // compile-time pruned
                float4 a = *reinterpret_cast<const float4*>(arow0 + (arl * KS + dj) * AS);
                acc0[0].x = fmaf(a.x, v[0 + dj].x, acc0[0].x);
                acc0[0].y = fmaf(a.x, v[0 + dj].y, acc0[0].y);
                acc0[0].z = fmaf(a.x, v[0 + dj].z, acc0[0].z);
                acc0[0].w = fmaf(a.x, v[0 + dj].w, acc0[0].w);
                acc0[1].x = fmaf(a.y, v[1 + dj].x, acc0[1].x);
                acc0[1].y = fmaf(a.y, v[1 + dj].y, acc0[1].y);
                acc0[1].z = fmaf(a.y, v[1 + dj].z, acc0[1].z);
                acc0[1].w = fmaf(a.y, v[1 + dj].w, acc0[1].w);
                acc0[2].x = fmaf(a.z, v[2 + dj].x, acc0[2].x);
                acc0[2].y = fmaf(a.z, v[2 + dj].y, acc0[2].y);
                acc0[2].z = fmaf(a.z, v[2 + dj].z, acc0[2].z);
                acc0[2].w = fmaf(a.z, v[2 + dj].w, acc0[2].w);
                acc0[3].x = fmaf(a.w, v[3 + dj].x, acc0[3].x);
                acc0[3].y = fmaf(a.w, v[3 + dj].y, acc0[3].y);
                acc0[3].z = fmaf(a.w, v[3 + dj].z, acc0[3].z);
                acc0[3].w = fmaf(a.w, v[3 + dj].w, acc0[3].w);
            }
            if (arl >= 1) {   // compile-time pruned
                float4 a = *reinterpret_cast<const float4*>(arow1 + ((arl - 1) * KS + dj) * AS);
                acc1[0].x = fmaf(a.x, v[0 + dj].x, acc1[0].x);
                acc1[0].y = fmaf(a.x, v[0 + dj].y, acc1[0].y);
                acc1[0].z = fmaf(a.x, v[0 + dj].z, acc1[0].z);
                acc1[0].w = fmaf(a.x, v[0 + dj].w, acc1[0].w);
                acc1[1].x = fmaf(a.y, v[1 + dj].x, acc1[1].x);
                acc1[1].y = fmaf(a.y, v[1 + dj].y, acc1[1].y);
                acc1[1].z = fmaf(a.y, v[1 + dj].z, acc1[1].z);
                acc1[1].w = fmaf(a.y, v[1 + dj].w, acc1[1].w);
                acc1[2].x = fmaf(a.z, v[2 + dj].x, acc1[2].x);
                acc1[2].y = fmaf(a.z, v[2 + dj].y, acc1[2].y);
                acc1[2].z = fmaf(a.z, v[2 + dj].z, acc1[2].z);
                acc1[2].w = fmaf(a.z, v[2 + dj].w, acc1[2].w);
                acc1[3].x = fmaf(a.w, v[3 + dj].x, acc1[3].x);
                acc1[3].y = fmaf(a.w, v[3 + dj].y, acc1[3].y);
                acc1[3].z = fmaf(a.w, v[3 + dj].z, acc1[3].z);
                acc1[3].w = fmaf(a.w, v[3 + dj].w, acc1[3].w);
            }
        }
    }

    // ---------- Epilogue: += attn[25]*current, direct coalesced float4 ----------
    const float* curb = curv + (size_t)b * H * W * BINS;
    float*       outb = out  + (size_t)b * H * W * BINS;
    #pragma unroll
    for (int rr = 0; rr < 2; ++rr) {
        float4 a25 = *reinterpret_cast<const float4*>(
            s_attn + 25 * AS + (r0 + rr) * TW + c0);
        const float* ap = &a25.x;
        float4* accp = (rr == 0) ? acc0 : acc1;
        #pragma unroll
        for (int p = 0; p < 4; ++p) {
            int gaddr = ((h0 + r0 + rr) * W + (w0 + c0 + p)) * BINS + bg * 4;
            float4 cv = *reinterpret_cast<const float4*>(curb + gaddr);
            float a = ap[p];
            float4 o;
            o.x = fmaf(a, cv.x, accp[p].x);
            o.y = fmaf(a, cv.y, accp[p].y);
            o.z = fmaf(a, cv.z, accp[p].z);
            o.w = fmaf(a, cv.w, accp[p].w);
            *reinterpret_cast<float4*>(outb + gaddr) = o;
        }
    }
}

extern "C" void kernel_launch(void* const* d_in, const int* in_sizes, int n_in,
                              void* d_out, int out_size) {
    const float* attn = (const float*)d_in[0];   // [4,128,128,26]
    const float* refv = (const float*)d_in[1];   // [4,128,128,64]
    const float* curv = (const float*)d_in[2];   // [4,128,128,64]
    float* out = (float*)d_out;                  // [4,128,128,64]

    cudaFuncSetAttribute(agg_kernel, cudaFuncAttributeMaxDynamicSharedMemorySize,
                         SMEM_BYTES);

    const int nblocks = B * (H / TH) * (W / TW);   // 4*16*8 = 512
    agg_kernel<<<nblocks, THREADS, SMEM_BYTES>>>(attn, refv, curv, out);
}